// round 4
// baseline (speedup 1.0000x reference)
#include <cuda_runtime.h>
#include <cstdint>

// Problem constants (fixed by the reference)
constexpr int B = 4;
constexpr int C = 32;
constexpr int GW = 64;               // W = L = H = 64
constexpr int LH = GW * GW;          // 4096
constexpr int V  = GW * GW * GW;     // 262144
constexpr unsigned MIN_PTS = 10;
constexpr unsigned KEY_NEG_INF = 0x007FFFFFu;  // encode(-inf)

// Per-voxel point counts, zeroed each launch by init_kernel.
__device__ unsigned int g_counts[B * V];

// ---------------------------------------------------------------------------
// Kernel 1: initialize voxeldata region of d_out with encode(-inf) keys and
// zero the count scratch. Vectorized uint4 stores.
// ---------------------------------------------------------------------------
__global__ void init_kernel(uint4* __restrict__ keys4, int n4_keys, int n4_counts) {
    int i = blockIdx.x * blockDim.x + threadIdx.x;
    const uint4 kinit = make_uint4(KEY_NEG_INF, KEY_NEG_INF, KEY_NEG_INF, KEY_NEG_INF);
    const uint4 zero  = make_uint4(0u, 0u, 0u, 0u);
    if (i < n4_keys)   keys4[i] = kinit;
    if (i < n4_counts) reinterpret_cast<uint4*>(g_counts)[i] = zero;
}

// ---------------------------------------------------------------------------
// Kernel 2: scatter points. One thread per (batch, point).
// float -> monotone uint key so atomicMax == float max (handles negatives).
// ---------------------------------------------------------------------------
__device__ __forceinline__ unsigned encode_f32(float f) {
    unsigned bits = __float_as_uint(f);
    return (bits & 0x80000000u) ? ~bits : (bits | 0x80000000u);
}

// Match XLA exactly: the algebraic simplifier folds (p - 0)/0.05f into
// p * (1/0.05f) where the f32-rounded reciprocal is exactly 20.0f, and the
// emitter produces separate rn-mul / rn-add (no FMA contraction). Intrinsics
// prevent nvcc from contracting this into an FMA.
__device__ __forceinline__ int voxelize(float p) {
    return (int)floorf(__fadd_rn(__fmul_rn(p, 20.0f), 0.5f));
}

__global__ void scatter_kernel(const float* __restrict__ coords,
                               const float* __restrict__ attrs,
                               unsigned int* __restrict__ out_keys,
                               int N) {
    int n = blockIdx.x * blockDim.x + threadIdx.x;
    int b = blockIdx.y;
    if (n >= N) return;

    const float* cb = coords + (size_t)b * 3 * N;
    int x = voxelize(cb[n]);
    int y = voxelize(cb[(size_t)N + n]);
    int z = voxelize(cb[(size_t)2 * N + n]);

    if ((unsigned)x < (unsigned)GW && (unsigned)y < (unsigned)GW &&
        (unsigned)z < (unsigned)GW) {
        int v = x * LH + y * GW + z;
        atomicAdd(&g_counts[b * V + v], 1u);

        const float* ab = attrs + (size_t)b * C * N + n;
        unsigned int* ob = out_keys + (size_t)b * C * V + v;
        #pragma unroll
        for (int c = 0; c < C; c++) {
            float a = ab[(size_t)c * N];           // coalesced across lanes
            atomicMax(&ob[(size_t)c * V], encode_f32(a));
        }
    }
}

// ---------------------------------------------------------------------------
// Kernel 3: decode keys in place (-> float voxeldata, 0 where empty) and
// write occupancy. One thread per (batch, voxel); coalesced across v.
// ---------------------------------------------------------------------------
__global__ void finalize_kernel(unsigned int* __restrict__ keys,
                                float* __restrict__ occ) {
    int idx = blockIdx.x * blockDim.x + threadIdx.x;   // over B*V
    if (idx >= B * V) return;
    int b = idx / V;
    int v = idx - b * V;

    unsigned cnt = g_counts[idx];
    occ[idx] = (cnt >= MIN_PTS) ? 1.0f : 0.0f;

    float* data = reinterpret_cast<float*>(keys);
    size_t base = (size_t)b * C * V + v;
    #pragma unroll
    for (int c = 0; c < C; c++) {
        size_t k = base + (size_t)c * V;
        float outv = 0.0f;
        if (cnt > 0u) {
            unsigned key = keys[k];
            unsigned bits = (key & 0x80000000u) ? (key ^ 0x80000000u) : ~key;
            outv = __uint_as_float(bits);
        }
        data[k] = outv;
    }
}

// ---------------------------------------------------------------------------
// Launch: d_out = [voxeldata (B*C*V f32)][occupancy (B*V f32)]
// ---------------------------------------------------------------------------
extern "C" void kernel_launch(void* const* d_in, const int* in_sizes, int n_in,
                              void* d_out, int out_size) {
    const float* coords = (const float*)d_in[0];   // [B,3,N]
    const float* attrs  = (const float*)d_in[1];   // [B,C,N]
    int N = in_sizes[0] / (B * 3);

    unsigned int* keys = (unsigned int*)d_out;
    float* occ = (float*)d_out + (size_t)B * C * V;

    int n4_keys   = (B * C * V) / 4;   // 8,388,608 uint4 stores
    int n4_counts = (B * V) / 4;       //   262,144 uint4 stores
    init_kernel<<<(n4_keys + 255) / 256, 256>>>(
        reinterpret_cast<uint4*>(keys), n4_keys, n4_counts);

    dim3 sg((N + 255) / 256, B);
    scatter_kernel<<<sg, 256>>>(coords, attrs, keys, N);

    finalize_kernel<<<(B * V + 255) / 256, 256>>>(keys, occ);
}

// round 5
// speedup vs baseline: 1.2507x; 1.2507x over previous
#include <cuda_runtime.h>
#include <cstdint>

// Problem constants (fixed by the reference)
constexpr int B = 4;
constexpr int C = 32;
constexpr int GW = 64;               // W = L = H = 64
constexpr int LH = GW * GW;          // 4096
constexpr int V  = GW * GW * GW;     // 262144
constexpr unsigned MIN_PTS = 10;
constexpr unsigned KEY_NEG_INF = 0x007FFFFFu;  // encode(-inf)

// Scratch: per-voxel channel maxes in [b][v][c] layout — one point's 32
// atomics hit ONE 128B cache line instead of 32 lines strided by 1MB.
__device__ unsigned int g_scratch[(size_t)B * V * C];
// Per-voxel point counts, zeroed each launch by init_kernel.
__device__ unsigned int g_counts[B * V];

// ---------------------------------------------------------------------------
// Kernel 1: initialize scratch with encode(-inf) keys and zero the counts.
// d_out needs no init — finalize_kernel overwrites every element.
// ---------------------------------------------------------------------------
__global__ void init_kernel(int n4_keys, int n4_counts) {
    int i = blockIdx.x * blockDim.x + threadIdx.x;
    const uint4 kinit = make_uint4(KEY_NEG_INF, KEY_NEG_INF, KEY_NEG_INF, KEY_NEG_INF);
    const uint4 zero  = make_uint4(0u, 0u, 0u, 0u);
    if (i < n4_keys)   reinterpret_cast<uint4*>(g_scratch)[i] = kinit;
    if (i < n4_counts) reinterpret_cast<uint4*>(g_counts)[i]  = zero;
}

// ---------------------------------------------------------------------------
// Kernel 2: scatter points. One thread per (batch, point).
// float -> monotone uint key so atomicMax == float max (handles negatives).
// ---------------------------------------------------------------------------
__device__ __forceinline__ unsigned encode_f32(float f) {
    unsigned bits = __float_as_uint(f);
    return (bits & 0x80000000u) ? ~bits : (bits | 0x80000000u);
}

// Match XLA exactly: (p - 0)/0.05f is simplified to p * (1/0.05f) with the
// f32-rounded reciprocal == exactly 20.0f, separate rn-mul / rn-add (no FMA).
__device__ __forceinline__ int voxelize(float p) {
    return (int)floorf(__fadd_rn(__fmul_rn(p, 20.0f), 0.5f));
}

__global__ void scatter_kernel(const float* __restrict__ coords,
                               const float* __restrict__ attrs,
                               int N) {
    int n = blockIdx.x * blockDim.x + threadIdx.x;
    int b = blockIdx.y;
    if (n >= N) return;

    const float* cb = coords + (size_t)b * 3 * N;
    int x = voxelize(cb[n]);
    int y = voxelize(cb[(size_t)N + n]);
    int z = voxelize(cb[(size_t)2 * N + n]);

    if ((unsigned)x < (unsigned)GW && (unsigned)y < (unsigned)GW &&
        (unsigned)z < (unsigned)GW) {
        int v = x * LH + y * GW + z;
        atomicAdd(&g_counts[b * V + v], 1u);

        const float* ab = attrs + (size_t)b * C * N + n;
        unsigned int* sb = g_scratch + ((size_t)b * V + v) * C;  // one 128B line
        #pragma unroll
        for (int c = 0; c < C; c++) {
            float a = ab[(size_t)c * N];        // coalesced across lanes
            atomicMax(&sb[c], encode_f32(a));   // RED.MAX, line-local
        }
    }
}

// ---------------------------------------------------------------------------
// Kernel 3: decode + transpose [b][v][c] scratch -> [b][c][v] output via
// shared-memory 32x32 tiles; write occupancy. Fully coalesced both sides.
// ---------------------------------------------------------------------------
constexpr int TV = 32;  // voxels per tile

__global__ void finalize_kernel(float* __restrict__ out, float* __restrict__ occ) {
    __shared__ float tile[TV][C + 1];
    __shared__ unsigned scnt[TV];

    int b  = blockIdx.y;
    int v0 = blockIdx.x * TV;
    int tx = threadIdx.x;            // 0..31
    int ty = threadIdx.y;            // 0..7

    if (ty == 0) scnt[tx] = g_counts[b * V + v0 + tx];
    __syncthreads();

    // Load: warp reads 32 consecutive channels of one voxel (one 128B line).
    const unsigned* sb = g_scratch + ((size_t)b * V + v0) * C;
    #pragma unroll
    for (int i = 0; i < TV; i += 8) {
        int v = i + ty;
        unsigned key = sb[(size_t)v * C + tx];
        float f = 0.0f;
        if (scnt[v] > 0u) {
            unsigned bits = (key & 0x80000000u) ? (key ^ 0x80000000u) : ~key;
            f = __uint_as_float(bits);
        }
        tile[v][tx] = f;
    }
    __syncthreads();

    // Store: warp writes 32 consecutive voxels of one channel (128B line).
    float* ob = out + (size_t)b * C * V + v0;
    #pragma unroll
    for (int i = 0; i < C; i += 8) {
        int c = i + ty;
        ob[(size_t)c * V + tx] = tile[tx][c];   // stride-33 smem read: no conflicts
    }

    if (ty == 0)
        occ[b * V + v0 + tx] = (scnt[tx] >= MIN_PTS) ? 1.0f : 0.0f;
}

// ---------------------------------------------------------------------------
// Launch: d_out = [voxeldata (B*C*V f32)][occupancy (B*V f32)]
// ---------------------------------------------------------------------------
extern "C" void kernel_launch(void* const* d_in, const int* in_sizes, int n_in,
                              void* d_out, int out_size) {
    const float* coords = (const float*)d_in[0];   // [B,3,N]
    const float* attrs  = (const float*)d_in[1];   // [B,C,N]
    int N = in_sizes[0] / (B * 3);

    float* voxeldata = (float*)d_out;
    float* occ       = (float*)d_out + (size_t)B * C * V;

    int n4_keys   = (B * V * C) / 4;   // 33,554,432 uint4 stores
    int n4_counts = (B * V) / 4;       //    262,144 uint4 stores
    init_kernel<<<(n4_keys + 255) / 256, 256>>>(n4_keys, n4_counts);

    dim3 sg((N + 255) / 256, B);
    scatter_kernel<<<sg, 256>>>(coords, attrs, N);

    dim3 fb(32, 8);
    dim3 fg(V / TV, B);
    finalize_kernel<<<fg, fb>>>(voxeldata, occ);
}

// round 8
// speedup vs baseline: 1.4680x; 1.1737x over previous
#include <cuda_runtime.h>
#include <cstdint>
#include <cmath>

// Problem constants (fixed by the reference)
constexpr int B  = 4;
constexpr int C  = 32;
constexpr int GW = 64;               // W = L = H = 64
constexpr int LH = GW * GW;          // 4096
constexpr int V  = GW * GW * GW;     // 262144
constexpr int BV = B * V;            // 1,048,576 = 1024 * 1024
constexpr int NMAX = 200000;
constexpr unsigned MIN_PTS = 10;

// Static scratch (no allocations allowed). All accessed ONLY from device code
// (passing __device__ symbols as kernel args from host is invalid).
__device__ float    g_attrT[(size_t)B * NMAX * C];  // [B][N][C] point-major attrs
__device__ int      g_vox   [B * NMAX];             // flat voxel id (b*V+v) or -1
__device__ unsigned g_counts[BV];                   // per-voxel point counts
__device__ unsigned g_offs  [BV];                   // block-local exclusive scan
__device__ unsigned g_bsums [1024];                 // per-scan-block sums
__device__ unsigned g_cursor[BV];                   // CSR fill cursor
__device__ int      g_order [B * NMAX];             // point indices grouped by voxel

// ---------------------------------------------------------------------------
// K1: zero counts
// ---------------------------------------------------------------------------
__global__ void zero_counts_kernel() {
    int i = blockIdx.x * blockDim.x + threadIdx.x;   // over BV/4
    reinterpret_cast<uint4*>(g_counts)[i] = make_uint4(0u, 0u, 0u, 0u);
}

// ---------------------------------------------------------------------------
// K2: transpose attrs [B][C][N] -> g_attrT [B][N][C] (32x32 smem tiles)
// N = 200000 is divisible by 32.
// ---------------------------------------------------------------------------
__global__ void transpose_kernel(const float* __restrict__ attrs, int N) {
    __shared__ float tile[C][33];
    int b  = blockIdx.y;
    int n0 = blockIdx.x * 32;
    int tx = threadIdx.x, ty = threadIdx.y;          // (32, 8)

    const float* ab = attrs + (size_t)b * C * N;
    #pragma unroll
    for (int j = 0; j < 4; j++) {
        int c = ty + 8 * j;
        tile[c][tx] = ab[(size_t)c * N + n0 + tx];   // coalesced over n
    }
    __syncthreads();
    float* ob = g_attrT + ((size_t)b * NMAX + n0) * C;
    #pragma unroll
    for (int j = 0; j < 4; j++) {
        int nl = ty + 8 * j;
        ob[(size_t)nl * C + tx] = tile[tx][nl];      // coalesced over c
    }
}

// ---------------------------------------------------------------------------
// K3: voxelize + histogram. Match XLA: (p-0)/0.05 folded to p * 20.0f
// (f32-rounded reciprocal is exactly 20.0f), separate rn-mul / rn-add.
// ---------------------------------------------------------------------------
__device__ __forceinline__ int voxelize(float p) {
    return (int)floorf(__fadd_rn(__fmul_rn(p, 20.0f), 0.5f));
}

__global__ void voxelize_count_kernel(const float* __restrict__ coords, int N) {
    int n = blockIdx.x * blockDim.x + threadIdx.x;
    int b = blockIdx.y;
    if (n >= N) return;

    const float* cb = coords + (size_t)b * 3 * N;
    int x = voxelize(cb[n]);
    int y = voxelize(cb[(size_t)N + n]);
    int z = voxelize(cb[(size_t)2 * N + n]);

    int bv = -1;
    if ((unsigned)x < (unsigned)GW && (unsigned)y < (unsigned)GW &&
        (unsigned)z < (unsigned)GW) {
        bv = b * V + x * LH + y * GW + z;
        atomicAdd(&g_counts[bv], 1u);
    }
    g_vox[b * NMAX + n] = bv;
}

// ---------------------------------------------------------------------------
// Block-level exclusive scan helper (1024 threads, 32 warps).
// Returns exclusive prefix for this thread; *total = block sum (valid in all
// threads after the call). Uses shfl + one smem round.
// ---------------------------------------------------------------------------
__device__ __forceinline__ unsigned block_exclusive_scan(unsigned v, unsigned* total) {
    __shared__ unsigned wsum[32];
    int tid  = threadIdx.x;
    int lane = tid & 31, wid = tid >> 5;

    unsigned x = v;
    #pragma unroll
    for (int d = 1; d < 32; d <<= 1) {
        unsigned t = __shfl_up_sync(0xffffffffu, x, d);
        if (lane >= d) x += t;
    }
    if (lane == 31) wsum[wid] = x;
    __syncthreads();
    if (wid == 0) {
        unsigned s = wsum[lane];
        #pragma unroll
        for (int d = 1; d < 32; d <<= 1) {
            unsigned t = __shfl_up_sync(0xffffffffu, s, d);
            if (lane >= d) s += t;
        }
        wsum[lane] = s;                    // inclusive warp-total prefix
    }
    __syncthreads();
    unsigned wp = (wid > 0) ? wsum[wid - 1] : 0u;
    *total = wsum[31];
    return wp + x - v;                     // exclusive prefix
}

// K4: per-1024-block exclusive scan of g_counts -> g_offs, block sums -> g_bsums
__global__ void scan_counts_kernel() {
    int i = blockIdx.x * 1024 + threadIdx.x;
    unsigned total;
    unsigned ex = block_exclusive_scan(g_counts[i], &total);
    g_offs[i] = ex;
    if (threadIdx.x == 0) g_bsums[blockIdx.x] = total;
}

// K5: exclusive scan of the 1024 block sums, in place (single block)
__global__ void scan_bsums_kernel() {
    unsigned total;
    unsigned ex = block_exclusive_scan(g_bsums[threadIdx.x], &total);
    __syncthreads();                       // all reads done before overwrite
    g_bsums[threadIdx.x] = ex;
}

// K6: cursor = global exclusive offset (block scan + block prefix)
__global__ void cursor_init_kernel() {
    int i = blockIdx.x * blockDim.x + threadIdx.x;   // over BV
    g_cursor[i] = g_offs[i] + g_bsums[i >> 10];
}

// ---------------------------------------------------------------------------
// K7: scatter point indices into CSR order.
// ---------------------------------------------------------------------------
__global__ void scatter_order_kernel(int N) {
    int n = blockIdx.x * blockDim.x + threadIdx.x;
    int b = blockIdx.y;
    if (n >= N) return;
    int bv = g_vox[b * NMAX + n];
    if (bv >= 0) {
        unsigned pos = atomicAdd(&g_cursor[bv], 1u);
        g_order[pos] = n;
    }
}

// ---------------------------------------------------------------------------
// K8: gather max per voxel (warp lanes = channels), smem transpose to
// [b][c][v] output, write occupancy. No value atomics, plain fmaxf.
// After K7, g_cursor[bv] == end offset; start = end - count.
// ---------------------------------------------------------------------------
__global__ void gather_finalize_kernel(float* __restrict__ out,
                                       float* __restrict__ occ) {
    __shared__ float    tile[32][C + 1];
    __shared__ unsigned scnt[32], send[32];

    int b  = blockIdx.y;
    int v0 = blockIdx.x * 32;
    int tx = threadIdx.x, ty = threadIdx.y;          // (32, 8)

    if (ty == 0) scnt[tx] = g_counts[b * V + v0 + tx];
    if (ty == 1) send[tx] = g_cursor[b * V + v0 + tx];
    __syncthreads();

    #pragma unroll
    for (int k = 0; k < 4; k++) {
        int vl = ty + 8 * k;                         // warp handles 4 voxels
        unsigned cnt = scnt[vl];
        unsigned start = send[vl] - cnt;
        float m = -INFINITY;
        for (unsigned i = 0; i < cnt; i++) {
            int n = g_order[start + i];              // warp-broadcast load
            m = fmaxf(m, g_attrT[((size_t)b * NMAX + n) * C + tx]);  // 1 line
        }
        tile[vl][tx] = (cnt > 0u) ? m : 0.0f;
    }
    __syncthreads();

    float* ob = out + (size_t)b * C * V + v0;
    #pragma unroll
    for (int j = 0; j < 4; j++) {
        int c = ty + 8 * j;
        ob[(size_t)c * V + tx] = tile[tx][c];        // coalesced over v
    }
    if (ty == 0)
        occ[b * V + v0 + tx] = (scnt[tx] >= MIN_PTS) ? 1.0f : 0.0f;
}

// ---------------------------------------------------------------------------
// Launch: d_out = [voxeldata (B*C*V f32)][occupancy (B*V f32)]
// ---------------------------------------------------------------------------
extern "C" void kernel_launch(void* const* d_in, const int* in_sizes, int n_in,
                              void* d_out, int out_size) {
    const float* coords = (const float*)d_in[0];   // [B,3,N]
    const float* attrs  = (const float*)d_in[1];   // [B,C,N]
    int N = in_sizes[0] / (B * 3);                 // 200000

    float* voxeldata = (float*)d_out;
    float* occ       = (float*)d_out + (size_t)B * C * V;

    zero_counts_kernel<<<BV / 4 / 256, 256>>>();

    dim3 tb(32, 8);
    dim3 tg(N / 32, B);
    transpose_kernel<<<tg, tb>>>(attrs, N);

    dim3 vg((N + 255) / 256, B);
    voxelize_count_kernel<<<vg, 256>>>(coords, N);

    scan_counts_kernel<<<1024, 1024>>>();
    scan_bsums_kernel<<<1, 1024>>>();
    cursor_init_kernel<<<BV / 256, 256>>>();

    scatter_order_kernel<<<vg, 256>>>(N);

    dim3 fg(V / 32, B);
    gather_finalize_kernel<<<fg, tb>>>(voxeldata, occ);
}

// round 9
// speedup vs baseline: 2.2279x; 1.5177x over previous
#include <cuda_runtime.h>
#include <cstdint>
#include <cmath>

// Problem constants (fixed by the reference)
constexpr int B  = 4;
constexpr int C  = 32;
constexpr int GW = 64;               // W = L = H = 64
constexpr int LH = GW * GW;          // 4096
constexpr int V  = GW * GW * GW;     // 262144
constexpr int BV = B * V;            // 1,048,576 = 1024 * 1024
constexpr int NMAX = 200000;
constexpr unsigned MIN_PTS = 10;

// Static scratch (no allocations allowed). Accessed ONLY from device code.
__device__ __align__(128) float g_csr[(size_t)B * NMAX * C]; // CSR-ordered attr lines
__device__ int      g_vox   [B * NMAX];             // flat voxel id (b*V+v) or -1
__device__ unsigned g_counts[BV];                   // per-voxel point counts
__device__ unsigned g_offs  [BV];                   // block-local exclusive scan
__device__ unsigned g_bsums [1024];                 // per-scan-block sums
__device__ unsigned g_cursor[BV];                   // CSR fill cursor

// ---------------------------------------------------------------------------
// K1: zero counts
// ---------------------------------------------------------------------------
__global__ void zero_counts_kernel() {
    int i = blockIdx.x * blockDim.x + threadIdx.x;   // over BV/4
    reinterpret_cast<uint4*>(g_counts)[i] = make_uint4(0u, 0u, 0u, 0u);
}

// ---------------------------------------------------------------------------
// K2: voxelize + histogram. Match XLA: (p-0)/0.05 folded to p * 20.0f
// (f32-rounded reciprocal is exactly 20.0f), separate rn-mul / rn-add.
// ---------------------------------------------------------------------------
__device__ __forceinline__ int voxelize(float p) {
    return (int)floorf(__fadd_rn(__fmul_rn(p, 20.0f), 0.5f));
}

__global__ void voxelize_count_kernel(const float* __restrict__ coords, int N) {
    int n = blockIdx.x * blockDim.x + threadIdx.x;
    int b = blockIdx.y;
    if (n >= N) return;

    const float* cb = coords + (size_t)b * 3 * N;
    int x = voxelize(cb[n]);
    int y = voxelize(cb[(size_t)N + n]);
    int z = voxelize(cb[(size_t)2 * N + n]);

    int bv = -1;
    if ((unsigned)x < (unsigned)GW && (unsigned)y < (unsigned)GW &&
        (unsigned)z < (unsigned)GW) {
        bv = b * V + x * LH + y * GW + z;
        atomicAdd(&g_counts[bv], 1u);
    }
    g_vox[b * NMAX + n] = bv;
}

// ---------------------------------------------------------------------------
// Block-level exclusive scan helper (1024 threads, 32 warps).
// ---------------------------------------------------------------------------
__device__ __forceinline__ unsigned block_exclusive_scan(unsigned v, unsigned* total) {
    __shared__ unsigned wsum[32];
    int tid  = threadIdx.x;
    int lane = tid & 31, wid = tid >> 5;

    unsigned x = v;
    #pragma unroll
    for (int d = 1; d < 32; d <<= 1) {
        unsigned t = __shfl_up_sync(0xffffffffu, x, d);
        if (lane >= d) x += t;
    }
    if (lane == 31) wsum[wid] = x;
    __syncthreads();
    if (wid == 0) {
        unsigned s = wsum[lane];
        #pragma unroll
        for (int d = 1; d < 32; d <<= 1) {
            unsigned t = __shfl_up_sync(0xffffffffu, s, d);
            if (lane >= d) s += t;
        }
        wsum[lane] = s;                    // inclusive warp-total prefix
    }
    __syncthreads();
    unsigned wp = (wid > 0) ? wsum[wid - 1] : 0u;
    *total = wsum[31];
    return wp + x - v;                     // exclusive prefix
}

// K3: per-1024-block exclusive scan of g_counts -> g_offs, block sums -> g_bsums
__global__ void scan_counts_kernel() {
    int i = blockIdx.x * 1024 + threadIdx.x;
    unsigned total;
    unsigned ex = block_exclusive_scan(g_counts[i], &total);
    g_offs[i] = ex;
    if (threadIdx.x == 0) g_bsums[blockIdx.x] = total;
}

// K4: exclusive scan of the 1024 block sums, in place (single block)
__global__ void scan_bsums_kernel() {
    unsigned total;
    unsigned ex = block_exclusive_scan(g_bsums[threadIdx.x], &total);
    __syncthreads();                       // all reads done before overwrite
    g_bsums[threadIdx.x] = ex;
}

// K5: cursor = global exclusive offset (block scan + block prefix)
__global__ void cursor_init_kernel() {
    int i = blockIdx.x * blockDim.x + threadIdx.x;   // over BV
    g_cursor[i] = g_offs[i] + g_bsums[i >> 10];
}

// ---------------------------------------------------------------------------
// K6: scatter attribute lines into CSR order. One thread per point.
// Reads attrs [B][C][N] coalesced across lanes (fixed c, consecutive n);
// writes one contiguous 128B line per point at its CSR slot.
// ---------------------------------------------------------------------------
__global__ void scatter_csr_kernel(const float* __restrict__ attrs, int N) {
    int n = blockIdx.x * blockDim.x + threadIdx.x;
    int b = blockIdx.y;
    if (n >= N) return;
    int bv = g_vox[b * NMAX + n];
    if (bv < 0) return;

    unsigned pos = atomicAdd(&g_cursor[bv], 1u);

    const float* ab = attrs + (size_t)b * C * N + n;
    float v[C];
    #pragma unroll
    for (int c = 0; c < C; c++) v[c] = ab[(size_t)c * N];   // coalesced

    float4* dst = reinterpret_cast<float4*>(g_csr + (size_t)pos * C);
    #pragma unroll
    for (int j = 0; j < C / 4; j++)
        dst[j] = make_float4(v[4*j], v[4*j+1], v[4*j+2], v[4*j+3]);
}

// ---------------------------------------------------------------------------
// K7: gather max per voxel (warp lanes = channels). Each warp owns 4 voxels,
// processed INTERLEAVED (4 independent predicated loads per step -> MLP=4,
// outer trip count = max of the 4 counts). CSR data is contiguous per voxel.
// After K6, g_cursor[bv] == end offset; start = end - count.
// ---------------------------------------------------------------------------
__global__ void gather_finalize_kernel(float* __restrict__ out,
                                       float* __restrict__ occ) {
    __shared__ float    tile[32][C + 1];
    __shared__ unsigned scnt[32], send[32];

    int b  = blockIdx.y;
    int v0 = blockIdx.x * 32;
    int tx = threadIdx.x, ty = threadIdx.y;          // (32, 8)

    if (ty == 0) scnt[tx] = g_counts[b * V + v0 + tx];
    if (ty == 1) send[tx] = g_cursor[b * V + v0 + tx];
    __syncthreads();

    unsigned cnt[4], start[4];
    float m[4];
    unsigned maxc = 0;
    #pragma unroll
    for (int k = 0; k < 4; k++) {
        int vl = ty + 8 * k;
        cnt[k]   = scnt[vl];
        start[k] = send[vl] - cnt[k];
        m[k]     = -INFINITY;
        maxc     = (cnt[k] > maxc) ? cnt[k] : maxc;
    }

    for (unsigned i = 0; i < maxc; i++) {
        #pragma unroll
        for (int k = 0; k < 4; k++) {
            if (i < cnt[k])                           // predicated, independent
                m[k] = fmaxf(m[k], g_csr[(size_t)(start[k] + i) * C + tx]);
        }
    }

    #pragma unroll
    for (int k = 0; k < 4; k++)
        tile[ty + 8 * k][tx] = (cnt[k] > 0u) ? m[k] : 0.0f;
    __syncthreads();

    float* ob = out + (size_t)b * C * V + v0;
    #pragma unroll
    for (int j = 0; j < 4; j++) {
        int c = ty + 8 * j;
        ob[(size_t)c * V + tx] = tile[tx][c];        // coalesced over v
    }
    if (ty == 0)
        occ[b * V + v0 + tx] = (scnt[tx] >= MIN_PTS) ? 1.0f : 0.0f;
}

// ---------------------------------------------------------------------------
// Launch: d_out = [voxeldata (B*C*V f32)][occupancy (B*V f32)]
// ---------------------------------------------------------------------------
extern "C" void kernel_launch(void* const* d_in, const int* in_sizes, int n_in,
                              void* d_out, int out_size) {
    const float* coords = (const float*)d_in[0];   // [B,3,N]
    const float* attrs  = (const float*)d_in[1];   // [B,C,N]
    int N = in_sizes[0] / (B * 3);                 // 200000

    float* voxeldata = (float*)d_out;
    float* occ       = (float*)d_out + (size_t)B * C * V;

    zero_counts_kernel<<<BV / 4 / 256, 256>>>();

    dim3 vg((N + 255) / 256, B);
    voxelize_count_kernel<<<vg, 256>>>(coords, N);

    scan_counts_kernel<<<1024, 1024>>>();
    scan_bsums_kernel<<<1, 1024>>>();
    cursor_init_kernel<<<BV / 256, 256>>>();

    scatter_csr_kernel<<<vg, 256>>>(attrs, N);

    dim3 fb(32, 8);
    dim3 fg(V / 32, B);
    gather_finalize_kernel<<<fg, fb>>>(voxeldata, occ);
}

// round 10
// speedup vs baseline: 2.2921x; 1.0288x over previous
#include <cuda_runtime.h>
#include <cstdint>
#include <cmath>

// Problem constants (fixed by the reference)
constexpr int B  = 4;
constexpr int C  = 32;
constexpr int GW = 64;               // W = L = H = 64
constexpr int LH = GW * GW;          // 4096
constexpr int V  = GW * GW * GW;     // 262144
constexpr int BV = B * V;            // 1,048,576 = 256 * 4096
constexpr int NMAX = 200000;
constexpr unsigned MIN_PTS = 10;
constexpr int SCAN_BLOCKS = 256;     // each scans 4096 counts (1024 thr x uint4)

// Static scratch (no allocations allowed). Accessed ONLY from device code.
__device__ __align__(128) float g_csr[(size_t)B * NMAX * C]; // CSR-ordered attr lines
__device__ int      g_vox   [B * NMAX];             // flat voxel id (b*V+v) or -1
__device__ unsigned g_counts[BV];                   // per-voxel point counts
__device__ unsigned g_offs  [BV];                   // block-local exclusive scan
__device__ unsigned g_bsums [SCAN_BLOCKS];          // per-scan-block sums
__device__ unsigned g_cursor[BV];                   // CSR fill cursor

// ---------------------------------------------------------------------------
// K1: zero counts
// ---------------------------------------------------------------------------
__global__ void zero_counts_kernel() {
    int i = blockIdx.x * blockDim.x + threadIdx.x;   // over BV/4
    reinterpret_cast<uint4*>(g_counts)[i] = make_uint4(0u, 0u, 0u, 0u);
}

// ---------------------------------------------------------------------------
// K2: voxelize + histogram. Match XLA: (p-0)/0.05 folded to p * 20.0f
// (f32-rounded reciprocal is exactly 20.0f), separate rn-mul / rn-add.
// ---------------------------------------------------------------------------
__device__ __forceinline__ int voxelize(float p) {
    return (int)floorf(__fadd_rn(__fmul_rn(p, 20.0f), 0.5f));
}

__global__ void voxelize_count_kernel(const float* __restrict__ coords, int N) {
    int n = blockIdx.x * blockDim.x + threadIdx.x;
    int b = blockIdx.y;
    if (n >= N) return;

    const float* cb = coords + (size_t)b * 3 * N;
    int x = voxelize(cb[n]);
    int y = voxelize(cb[(size_t)N + n]);
    int z = voxelize(cb[(size_t)2 * N + n]);

    int bv = -1;
    if ((unsigned)x < (unsigned)GW && (unsigned)y < (unsigned)GW &&
        (unsigned)z < (unsigned)GW) {
        bv = b * V + x * LH + y * GW + z;
        atomicAdd(&g_counts[bv], 1u);
    }
    g_vox[b * NMAX + n] = bv;
}

// ---------------------------------------------------------------------------
// Block-level exclusive scan helper (1024 threads, 32 warps).
// ---------------------------------------------------------------------------
__device__ __forceinline__ unsigned block_exclusive_scan(unsigned v, unsigned* total) {
    __shared__ unsigned wsum[32];
    int tid  = threadIdx.x;
    int lane = tid & 31, wid = tid >> 5;

    unsigned x = v;
    #pragma unroll
    for (int d = 1; d < 32; d <<= 1) {
        unsigned t = __shfl_up_sync(0xffffffffu, x, d);
        if (lane >= d) x += t;
    }
    if (lane == 31) wsum[wid] = x;
    __syncthreads();
    if (wid == 0) {
        unsigned s = wsum[lane];
        #pragma unroll
        for (int d = 1; d < 32; d <<= 1) {
            unsigned t = __shfl_up_sync(0xffffffffu, s, d);
            if (lane >= d) s += t;
        }
        wsum[lane] = s;                    // inclusive warp-total prefix
    }
    __syncthreads();
    unsigned wp = (wid > 0) ? wsum[wid - 1] : 0u;
    *total = wsum[31];
    return wp + x - v;                     // exclusive prefix
}

// ---------------------------------------------------------------------------
// K3: exclusive scan of g_counts, 4 counts/thread (uint4), 256 blocks x 1024.
// Writes block-local exclusive prefixes to g_offs and block sums to g_bsums.
// ---------------------------------------------------------------------------
__global__ void scan_counts_kernel() {
    int tid = threadIdx.x;
    int i4  = blockIdx.x * 1024 + tid;               // uint4 index, BV/4 total
    uint4 c = reinterpret_cast<const uint4*>(g_counts)[i4];
    unsigned tsum = c.x + c.y + c.z + c.w;

    unsigned total;
    unsigned ex = block_exclusive_scan(tsum, &total);

    uint4 o;
    o.x = ex;
    o.y = o.x + c.x;
    o.z = o.y + c.y;
    o.w = o.z + c.z;
    reinterpret_cast<uint4*>(g_offs)[i4] = o;
    if (tid == 0) g_bsums[blockIdx.x] = total;
}

// ---------------------------------------------------------------------------
// K4: cursor init. Each block (matching a scan block's 4096-count range)
// computes its scalar prefix = sum(g_bsums[0..blk-1]) via an in-block masked
// reduction (bsums is 1KB, L2-hot), then g_cursor = g_offs + prefix (uint4).
// Replaces the old scan_bsums + cursor_init pair.
// ---------------------------------------------------------------------------
__global__ void cursor_init_kernel() {
    __shared__ unsigned wred[32];
    __shared__ unsigned s_prefix;
    int tid  = threadIdx.x;
    int blk  = blockIdx.x;
    int lane = tid & 31, wid = tid >> 5;

    unsigned v = (tid < blk) ? g_bsums[tid] : 0u;    // tid<256 covers all sums
    #pragma unroll
    for (int d = 16; d > 0; d >>= 1)
        v += __shfl_down_sync(0xffffffffu, v, d);
    if (lane == 0) wred[wid] = v;
    __syncthreads();
    if (wid == 0) {
        unsigned s = wred[lane];
        #pragma unroll
        for (int d = 16; d > 0; d >>= 1)
            s += __shfl_down_sync(0xffffffffu, s, d);
        if (lane == 0) s_prefix = s;
    }
    __syncthreads();

    unsigned p = s_prefix;
    int i4 = blk * 1024 + tid;
    uint4 o = reinterpret_cast<const uint4*>(g_offs)[i4];
    reinterpret_cast<uint4*>(g_cursor)[i4] =
        make_uint4(o.x + p, o.y + p, o.z + p, o.w + p);
}

// ---------------------------------------------------------------------------
// K5: scatter attribute lines into CSR order. One thread per point.
// Reads attrs [B][C][N] coalesced across lanes (fixed c, consecutive n);
// writes one contiguous 128B line per point at its CSR slot.
// ---------------------------------------------------------------------------
__global__ void scatter_csr_kernel(const float* __restrict__ attrs, int N) {
    int n = blockIdx.x * blockDim.x + threadIdx.x;
    int b = blockIdx.y;
    if (n >= N) return;
    int bv = g_vox[b * NMAX + n];
    if (bv < 0) return;

    unsigned pos = atomicAdd(&g_cursor[bv], 1u);

    const float* ab = attrs + (size_t)b * C * N + n;
    float v[C];
    #pragma unroll
    for (int c = 0; c < C; c++) v[c] = ab[(size_t)c * N];   // coalesced

    float4* dst = reinterpret_cast<float4*>(g_csr + (size_t)pos * C);
    #pragma unroll
    for (int j = 0; j < C / 4; j++)
        dst[j] = make_float4(v[4*j], v[4*j+1], v[4*j+2], v[4*j+3]);
}

// ---------------------------------------------------------------------------
// K6: gather max per voxel (warp lanes = channels). Each warp owns 4 voxels,
// processed INTERLEAVED (4 independent predicated loads per step -> MLP=4,
// outer trip count = max of the 4 counts). CSR data is contiguous per voxel.
// After K5, g_cursor[bv] == end offset; start = end - count.
// ---------------------------------------------------------------------------
__global__ void gather_finalize_kernel(float* __restrict__ out,
                                       float* __restrict__ occ) {
    __shared__ float    tile[32][C + 1];
    __shared__ unsigned scnt[32], send[32];

    int b  = blockIdx.y;
    int v0 = blockIdx.x * 32;
    int tx = threadIdx.x, ty = threadIdx.y;          // (32, 8)

    if (ty == 0) scnt[tx] = g_counts[b * V + v0 + tx];
    if (ty == 1) send[tx] = g_cursor[b * V + v0 + tx];
    __syncthreads();

    unsigned cnt[4], start[4];
    float m[4];
    unsigned maxc = 0;
    #pragma unroll
    for (int k = 0; k < 4; k++) {
        int vl = ty + 8 * k;
        cnt[k]   = scnt[vl];
        start[k] = send[vl] - cnt[k];
        m[k]     = -INFINITY;
        maxc     = (cnt[k] > maxc) ? cnt[k] : maxc;
    }

    for (unsigned i = 0; i < maxc; i++) {
        #pragma unroll
        for (int k = 0; k < 4; k++) {
            if (i < cnt[k])                           // predicated, independent
                m[k] = fmaxf(m[k], g_csr[(size_t)(start[k] + i) * C + tx]);
        }
    }

    #pragma unroll
    for (int k = 0; k < 4; k++)
        tile[ty + 8 * k][tx] = (cnt[k] > 0u) ? m[k] : 0.0f;
    __syncthreads();

    float* ob = out + (size_t)b * C * V + v0;
    #pragma unroll
    for (int j = 0; j < 4; j++) {
        int c = ty + 8 * j;
        ob[(size_t)c * V + tx] = tile[tx][c];        // coalesced over v
    }
    if (ty == 0)
        occ[b * V + v0 + tx] = (scnt[tx] >= MIN_PTS) ? 1.0f : 0.0f;
}

// ---------------------------------------------------------------------------
// Launch: d_out = [voxeldata (B*C*V f32)][occupancy (B*V f32)]
// ---------------------------------------------------------------------------
extern "C" void kernel_launch(void* const* d_in, const int* in_sizes, int n_in,
                              void* d_out, int out_size) {
    const float* coords = (const float*)d_in[0];   // [B,3,N]
    const float* attrs  = (const float*)d_in[1];   // [B,C,N]
    int N = in_sizes[0] / (B * 3);                 // 200000

    float* voxeldata = (float*)d_out;
    float* occ       = (float*)d_out + (size_t)B * C * V;

    zero_counts_kernel<<<BV / 4 / 256, 256>>>();

    dim3 vg((N + 255) / 256, B);
    voxelize_count_kernel<<<vg, 256>>>(coords, N);

    scan_counts_kernel<<<SCAN_BLOCKS, 1024>>>();
    cursor_init_kernel<<<SCAN_BLOCKS, 1024>>>();

    scatter_csr_kernel<<<vg, 256>>>(attrs, N);

    dim3 fb(32, 8);
    dim3 fg(V / 32, B);
    gather_finalize_kernel<<<fg, fb>>>(voxeldata, occ);
}